// round 13
// baseline (speedup 1.0000x reference)
#include <cuda_runtime.h>

typedef unsigned long long u64;

#define HW   64
#define F    64
#define D    75
#define KR   5
#define NROW 15
#define SXW  68          // full row + 4 halo
#define NTHR 256

// u64 offsets
#define WPU  0           // WP pairs [75][33] u64 (stride-33 pad) = 2475
#define XPU  2476        // patch dup [15][68] u64 = 1020 (16B-aligned base)
#define SWU  3496        // w2 partials [8][32] u64 = 256
#define X2U  3752        // x2: 64 f32 = 32 u64
#define SMEM_U64 3784    // 30272 B
// f32 aliases over WP (dead after main loop)
#define FLO  0           // [64][33] f32 = 2112
#define FHI  2112        // [64][33] f32 (ends at f32 4224 = u64 2112 < 2475)

__global__ __launch_bounds__(NTHR, 4)
void euclid2d_kernel(const float* __restrict__ x,
                     const float* __restrict__ W,
                     float* __restrict__ out) {
    __shared__ __align__(16) u64 S[SMEM_U64];
    float* Sf = (float*)S;

    const int tid  = threadIdx.x;
    const int lane = tid & 31;
    const int w    = tid >> 5;        // warp 0..7 -> pixels w*8..w*8+7
    const int ho   = blockIdx.x;      // 0..63
    const int n    = blockIdx.y;      // 0..7

    // ---- patch tile (duplicated pairs), full 64-px row ----
    {
        const int y0 = ho - 2;
        #pragma unroll
        for (int k = 0; k < 4; k++) {
            int i = tid + k * NTHR;            // 0..1019
            if (i < NROW * SXW) {
                int row = i / SXW;
                int col = i % SXW;
                int gy = y0 + (row % KR);
                int gx = col - 2;
                float v = 0.0f;
                if (gy >= 0 && gy < HW && gx >= 0 && gx < HW)
                    v = x[((n * 3 + (row / KR)) * HW + gy) * HW + gx];
                u64 p;
                asm("mov.b64 %0, {%1, %1};" : "=l"(p) : "f"(v));
                S[XPU + i] = p;
            }
        }
    }

    // ---- direct W transpose: lane = d -> coalesced LDG, conflict-free STS.64 ----
    #pragma unroll
    for (int it = 0; it < 12; it++) {
        int t    = w + 8 * it;
        int fp   = t & 31;
        int dblk = t >> 5;
        int d    = dblk * 32 + lane;
        if (d < D) {
            float lo = W[(2 * fp)     * D + d];   // lane-consecutive
            float hi = W[(2 * fp + 1) * D + d];   // lane-consecutive
            u64 p;
            asm("mov.b64 %0, {%1, %2};" : "=l"(p) : "f"(lo), "f"(hi));
            S[WPU + d * 33 + fp] = p;             // stride-33: conflict-free
        }
    }
    __syncthreads();   // barrier 1: WP + patch ready

    // ---- x2 partials (4 thr/px, shfl) and w2 partials (8-way d-split) ----
    {
        const int px = tid >> 2;               // 0..63
        const int q  = tid & 3;
        float s = 0.0f;
        #pragma unroll
        for (int k = 0; k < 19; k++) {
            int d = q + 4 * k;
            if (d < D) {
                int row = d / KR, kw = d % KR;
                float v = Sf[(XPU + row * SXW + px + kw) * 2];
                s += v * v;
            }
        }
        s += __shfl_xor_sync(0xffffffffu, s, 1);
        s += __shfl_xor_sync(0xffffffffu, s, 2);
        if (q == 0) Sf[X2U * 2 + px] = s;
    }
    {
        int fp = tid & 31, q = tid >> 5;       // q = 0..7
        u64 a = 0ULL;
        #pragma unroll
        for (int k = 0; k < 10; k++) {
            int d = q + 8 * k;
            if (d < D) {
                u64 wv = S[WPU + d * 33 + fp];
                asm("fma.rn.f32x2 %0, %1, %1, %0;" : "+l"(a) : "l"(wv));
            }
        }
        S[SWU + q * 32 + fp] = a;
    }
    __syncthreads();   // barrier 2: partials ready

    // ---- main loop: per row, batch ALL 11 loads (MLP=11), then 40 FFMA2 ----
    u64 acc[8];
    #pragma unroll
    for (int p = 0; p < 8; p++) acc[p] = 0ULL;

    #pragma unroll
    for (int row = 0; row < NROW; row++) {
        // 5 weight pairs for this row: independent conflict-free LDS.64
        u64 wv[5];
        #pragma unroll
        for (int kw = 0; kw < KR; kw++)
            wv[kw] = S[WPU + (row * KR + kw) * 33 + lane];
        // 6 patch broadcasts: independent LDS.128
        const ulonglong2* prow = (const ulonglong2*)&S[XPU + row * SXW + w * 8];
        ulonglong2 P2[6];
        #pragma unroll
        for (int t = 0; t < 6; t++) P2[t] = prow[t];
        const u64* Pu = (const u64*)P2;                      // 12 u64
        #pragma unroll
        for (int kw = 0; kw < KR; kw++) {
            #pragma unroll
            for (int p = 0; p < 8; p++)
                asm("fma.rn.f32x2 %0, %1, %2, %0;"
                    : "+l"(acc[p]) : "l"(Pu[kw + p]), "l"(wv[kw]));
        }
    }

    // ---- epilogue: w2 from 8 partials, res, padded transpose ----
    {
        u64 w2l = S[SWU + lane];
        #pragma unroll
        for (int q = 1; q < 8; q++) {
            u64 aq = S[SWU + q * 32 + lane];
            asm("add.rn.f32x2 %0, %0, %1;" : "+l"(w2l) : "l"(aq));
        }
        u64 nh;
        { float mh = -0.5f; asm("mov.b64 %0, {%1, %1};" : "=l"(nh) : "f"(mh)); }
        float x2v[8];
        #pragma unroll
        for (int p = 0; p < 8; p++) x2v[p] = Sf[X2U * 2 + w * 8 + p];
        __syncthreads();   // barrier 3: all WP/partial reads done before aliasing
        #pragma unroll
        for (int p = 0; p < 8; p++) {
            int px = w * 8 + p;
            u64 x2d, s, r = acc[p];
            asm("mov.b64 %0, {%1, %1};" : "=l"(x2d) : "f"(x2v[p]));
            asm("add.rn.f32x2 %0, %1, %2;" : "=l"(s) : "l"(x2d), "l"(w2l));
            asm("fma.rn.f32x2 %0, %1, %2, %0;" : "+l"(r) : "l"(s), "l"(nh));
            float lo, hi;
            asm("mov.b64 {%0, %1}, %2;" : "=f"(lo), "=f"(hi) : "l"(r));
            Sf[FLO + px * 33 + lane] = lo;    // conflict-free
            Sf[FHI + px * 33 + lane] = hi;
        }
    }
    __syncthreads();   // barrier 4: transpose buffer ready

    // ---- store: lane = pixel -> contiguous 128B runs ----
    #pragma unroll
    for (int k = 0; k < 4; k++) {
        int fp = w + 8 * k;
        float* o0 = out + (((long)(n * F + 2 * fp)     * HW + ho) * HW);
        float* o1 = out + (((long)(n * F + 2 * fp + 1) * HW + ho) * HW);
        #pragma unroll
        for (int half = 0; half < 2; half++) {
            int px = half * 32 + lane;
            o0[px] = Sf[FLO + px * 33 + fp];
            o1[px] = Sf[FHI + px * 33 + fp];
        }
    }
}

extern "C" void kernel_launch(void* const* d_in, const int* in_sizes, int n_in,
                              void* d_out, int out_size) {
    const float* x = (const float*)d_in[0];
    const float* W = (const float*)d_in[1];
    float* out = (float*)d_out;

    dim3 grid(HW, 8);    // 512 CTAs
    euclid2d_kernel<<<grid, NTHR>>>(x, W, out);
}

// round 14
// speedup vs baseline: 1.5009x; 1.5009x over previous
#include <cuda_runtime.h>

typedef unsigned long long u64;

#define HW   64
#define F    64
#define D    75
#define KR   5
#define SXW  68          // full row + 4 halo
#define NTHR 512

// u64 offsets
#define WPU  0           // WP pairs [75][33] u64 = 2475
#define XPU  2476        // patch dup [3][6][68] u64 = 1224 (16B-aligned)
#define SWU  3700        // w2 partials [8][32] u64 = 256
#define X2U  3956        // x2: 128 f32 = 64 u64
#define SMEM_U64 4020    // 32160 B
// f32 alias over WP region (dead after main loop): BUF [128][33] f32 = 2112 u64
#define BUF  0

__global__ __launch_bounds__(NTHR, 2)
void euclid2d_kernel(const float* __restrict__ x,
                     const float* __restrict__ W,
                     float* __restrict__ out) {
    __shared__ __align__(16) u64 S[SMEM_U64];
    float* Sf = (float*)S;

    const int tid  = threadIdx.x;
    const int lane = tid & 31;
    const int w    = tid >> 5;        // warp 0..15
    const int r0   = blockIdx.x * 2;  // output rows r0, r0+1
    const int n    = blockIdx.y;      // 0..7

    // ---- patch tile: 3ch x 6 rows x 68 cols, duplicated (v,v) pairs ----
    {
        const int y0 = r0 - 2;
        #pragma unroll
        for (int k = 0; k < 3; k++) {
            int i = tid + k * NTHR;            // 0..1223
            if (i < 3 * 6 * SXW) {
                int row = i / SXW;
                int col = i % SXW;
                int c = row / 6, rr = row % 6;
                int gy = y0 + rr, gx = col - 2;
                float v = 0.0f;
                if (gy >= 0 && gy < HW && gx >= 0 && gx < HW)
                    v = x[((n * 3 + c) * HW + gy) * HW + gx];
                u64 p;
                asm("mov.b64 %0, {%1, %1};" : "=l"(p) : "f"(v));
                S[XPU + i] = p;
            }
        }
    }

    // ---- direct W transpose: lane = d -> coalesced LDG, conflict-free STS.64 ----
    #pragma unroll
    for (int it = 0; it < 6; it++) {
        int t    = w + 16 * it;          // tasks 0..95
        int fp   = t & 31;
        int dblk = t >> 5;
        int d    = dblk * 32 + lane;
        if (d < D) {
            float lo = W[(2 * fp)     * D + d];
            float hi = W[(2 * fp + 1) * D + d];
            u64 p;
            asm("mov.b64 %0, {%1, %2};" : "=l"(p) : "f"(lo), "f"(hi));
            S[WPU + d * 33 + fp] = p;
        }
    }
    __syncthreads();   // B1: patch + WP ready

    // ---- x2 per pixel-row-pair (4 thr/px over 128 px) ----
    {
        const int px = tid >> 2;          // 0..127 (= r*64 + p)
        const int q  = tid & 3;
        const int r  = px >> 6, p = px & 63;
        float s = 0.0f;
        #pragma unroll
        for (int k = 0; k < 19; k++) {
            int d = q + 4 * k;
            if (d < D) {
                int c = d / 25, kh = (d % 25) / 5, kw = d % 5;
                float v = Sf[(XPU + (c * 6 + kh + r) * SXW + p + kw) * 2];
                s += v * v;
            }
        }
        s += __shfl_xor_sync(0xffffffffu, s, 1);
        s += __shfl_xor_sync(0xffffffffu, s, 2);
        if (q == 0) Sf[X2U * 2 + px] = s;
    }
    // ---- w2 partials (8-way d-split, first 8 warps) ----
    if (tid < 256) {
        int fp = tid & 31, q = tid >> 5;
        u64 a = 0ULL;
        #pragma unroll
        for (int k = 0; k < 10; k++) {
            int d = q + 8 * k;
            if (d < D) {
                u64 wv = S[WPU + d * 33 + fp];
                asm("fma.rn.f32x2 %0, %1, %1, %0;" : "+l"(a) : "l"(wv));
            }
        }
        S[SWU + q * 32 + fp] = a;
    }
    // (no barrier: main loop reads only WP/XP, already fenced by B1)

    // ---- main loop: warp w -> row r = w>>3, pixel chunk (w&7)*8 ----
    u64 acc[8];
    #pragma unroll
    for (int p = 0; p < 8; p++) acc[p] = 0ULL;
    {
        const int r = w >> 3, chunk = w & 7;
        #pragma unroll
        for (int c = 0; c < 3; c++)
            #pragma unroll
            for (int kh = 0; kh < KR; kh++) {
                const ulonglong2* prow =
                    (const ulonglong2*)&S[XPU + (c * 6 + kh + r) * SXW + chunk * 8];
                ulonglong2 P2[6];
                #pragma unroll
                for (int t = 0; t < 6; t++) P2[t] = prow[t];   // broadcast LDS.128
                const u64* Pu = (const u64*)P2;
                #pragma unroll
                for (int kw = 0; kw < KR; kw++) {
                    u64 wv = S[WPU + (c * 25 + kh * 5 + kw) * 33 + lane];
                    #pragma unroll
                    for (int p = 0; p < 8; p++)
                        asm("fma.rn.f32x2 %0, %1, %2, %0;"
                            : "+l"(acc[p]) : "l"(Pu[kw + p]), "l"(wv));
                }
            }
    }

    // ---- epilogue ----
    float lov[8], hiv[8];
    {
        __syncthreads();   // B2: partials ready; all WP/XP reads done (alias-safe)
        u64 w2l = S[SWU + lane];
        #pragma unroll
        for (int q = 1; q < 8; q++) {
            u64 aq = S[SWU + q * 32 + lane];
            asm("add.rn.f32x2 %0, %0, %1;" : "+l"(w2l) : "l"(aq));
        }
        u64 nh;
        { float mh = -0.5f; asm("mov.b64 %0, {%1, %1};" : "=l"(nh) : "f"(mh)); }
        const int r = w >> 3, chunk = w & 7;
        #pragma unroll
        for (int p = 0; p < 8; p++) {
            int pxg = r * 64 + chunk * 8 + p;
            float x2 = Sf[X2U * 2 + pxg];
            u64 x2d, s, rr = acc[p];
            asm("mov.b64 %0, {%1, %1};" : "=l"(x2d) : "f"(x2));
            asm("add.rn.f32x2 %0, %1, %2;" : "=l"(s) : "l"(x2d), "l"(w2l));
            asm("fma.rn.f32x2 %0, %1, %2, %0;" : "+l"(rr) : "l"(s), "l"(nh));
            asm("mov.b64 {%0, %1}, %2;" : "=f"(lov[p]), "=f"(hiv[p]) : "l"(rr));
            Sf[BUF + pxg * 33 + lane] = lov[p];   // conflict-free STS
        }
    }
    __syncthreads();   // B3: lo buffer ready

    // ---- store lo (even filters) ----
    #pragma unroll
    for (int it = 0; it < 8; it++) {
        int tt   = w + 16 * it;          // 0..127
        int fp   = tt >> 2;
        int r    = (tt >> 1) & 1;
        int half = tt & 1;
        int px   = half * 32 + lane;
        float v = Sf[BUF + (r * 64 + px) * 33 + fp];
        out[(((long)(n * F + 2 * fp) * HW) + (r0 + r)) * HW + px] = v;
    }
    __syncthreads();   // B4: lo reads done

    // ---- write hi buffer ----
    {
        const int r = w >> 3, chunk = w & 7;
        #pragma unroll
        for (int p = 0; p < 8; p++)
            Sf[BUF + (r * 64 + chunk * 8 + p) * 33 + lane] = hiv[p];
    }
    __syncthreads();   // B5: hi buffer ready

    // ---- store hi (odd filters) ----
    #pragma unroll
    for (int it = 0; it < 8; it++) {
        int tt   = w + 16 * it;
        int fp   = tt >> 2;
        int r    = (tt >> 1) & 1;
        int half = tt & 1;
        int px   = half * 32 + lane;
        float v = Sf[BUF + (r * 64 + px) * 33 + fp];
        out[(((long)(n * F + 2 * fp + 1) * HW) + (r0 + r)) * HW + px] = v;
    }
}

extern "C" void kernel_launch(void* const* d_in, const int* in_sizes, int n_in,
                              void* d_out, int out_size) {
    const float* x = (const float*)d_in[0];
    const float* W = (const float*)d_in[1];
    float* out = (float*)d_out;

    dim3 grid(HW / 2, 8);   // 256 CTAs, 512 threads
    euclid2d_kernel<<<grid, NTHR>>>(x, W, out);
}

// round 16
// speedup vs baseline: 1.6794x; 1.1189x over previous
#include <cuda_runtime.h>
#include <cstdint>

#define HW   64
#define F    64
#define D    75
#define KSTR 84          // smem K stride (g*20+t mod32 -> conflict-free frags)
#define NTHR 256

// byte offsets in dynamic smem
#define A_OFF   0                       // W tf32 [64][84]  = 21504 B
#define B_OFF   21504                   // Xcol tf32 [128][84] = 43008 B
#define XT_OFF  64512                   // xtile [3][6][68] f32 = 4896 B
#define X2_OFF  69408                   // x2[128] f32
#define W2P_OFF 69920                   // w2 partials [4][64]
#define W2_OFF  70944                   // w2[64]
#define SMEM_BYTES 71200

__device__ __forceinline__ uint32_t to_tf32(float v) {
    uint32_t r;
    asm("cvt.rna.tf32.f32 %0, %1;" : "=r"(r) : "f"(v));
    return r;
}

__global__ __launch_bounds__(NTHR)
void euclid2d_kernel(const float* __restrict__ x,
                     const float* __restrict__ W,
                     float* __restrict__ out) {
    extern __shared__ __align__(16) char smem[];
    float* Sf = (float*)smem;
    uint32_t* Su = (uint32_t*)smem;

    const int tid  = threadIdx.x;
    const int lane = tid & 31;
    const int wid  = tid >> 5;
    const int r0   = blockIdx.x * 2;   // output rows r0, r0+1
    const int n    = blockIdx.y;

    // ---- zero A+B (covers K pad 75..79), load x tile ----
    {
        uint4 z = make_uint4(0, 0, 0, 0);
        uint4* ab = (uint4*)smem;      // A and B contiguous: 16128 f32 = 4032 uint4
        #pragma unroll
        for (int i = 0; i < 16; i++) {
            int j = tid + i * NTHR;
            if (j < 4032) ab[j] = z;
        }
    }
    {
        float* xt = Sf + XT_OFF / 4;
        const int y0 = r0 - 2;
        #pragma unroll
        for (int i = 0; i < 5; i++) {
            int idx = tid + i * NTHR;          // 0..1223
            if (idx < 3 * 6 * 68) {
                int c = idx / (6 * 68);
                int rr = (idx / 68) % 6;
                int col = idx % 68;
                int gy = y0 + rr, gx = col - 2;
                float v = 0.0f;
                if (gy >= 0 && gy < HW && gx >= 0 && gx < HW)
                    v = x[((n * 3 + c) * HW + gy) * HW + gx];
                xt[idx] = v;
            }
        }
    }
    __syncthreads();   // S1

    // ---- fill A = tf32(W), w2 partials (exact fp32) ----
    #pragma unroll
    for (int i = 0; i < 19; i++) {
        int idx = tid + i * NTHR;
        if (idx < F * D) {
            int f = idx / D, k = idx % D;
            Su[A_OFF / 4 + f * KSTR + k] = to_tf32(W[idx]);
        }
    }
    {
        int f = tid & 63, q = tid >> 6;
        float s = 0.0f;
        #pragma unroll
        for (int i = 0; i < 19; i++) {
            int d = q + 4 * i;
            if (d < D) { float wv = W[f * D + d]; s += wv * wv; }
        }
        Sf[W2P_OFF / 4 + q * 64 + f] = s;
    }
    // ---- fill B = tf32(im2col), fused exact x2 ----
    {
        float* xt = Sf + XT_OFF / 4;
        const int px = tid >> 1;           // 0..127
        const int q  = tid & 1;
        const int r  = px >> 6, p = px & 63;
        float s = 0.0f;
        #pragma unroll
        for (int i = 0; i < 38; i++) {
            int k = q * 38 + i;
            if (k < D) {
                int c = k / 25, kh = (k % 25) / 5, kw = k % 5;
                float v = xt[(c * 6 + r + kh) * 68 + p + kw];
                Su[B_OFF / 4 + px * KSTR + k] = to_tf32(v);
                s += v * v;
            }
        }
        s += __shfl_xor_sync(0xffffffffu, s, 1);
        if (q == 0) Sf[X2_OFF / 4 + px] = s;
    }
    __syncthreads();   // S2

    if (tid < 64)
        Sf[W2_OFF / 4 + tid] = Sf[W2P_OFF / 4 + tid] + Sf[W2P_OFF / 4 + 64 + tid]
                             + Sf[W2P_OFF / 4 + 128 + tid] + Sf[W2P_OFF / 4 + 192 + tid];
    __syncthreads();   // S3

    // ---- warp tile: wid = mrow(0..3) + 4*ncol(0..1); M16 x N64 ----
    const int mrow = wid & 3;          // f0 = mrow*16
    const int ncol = wid >> 2;         // output row r0+ncol, px base ncol*64
    const int f0   = mrow * 16;
    const int g    = lane >> 2;        // 0..7
    const int t    = lane & 3;         // 0..3

    float acc[8][4];
    #pragma unroll
    for (int s = 0; s < 8; s++)
        #pragma unroll
        for (int j = 0; j < 4; j++) acc[s][j] = 0.0f;

    const uint32_t* SA = Su + A_OFF / 4;
    const uint32_t* SB = Su + B_OFF / 4 + (ncol * 64) * KSTR;

    #pragma unroll
    for (int ks = 0; ks < 10; ks++) {
        const int k0 = ks * 8;
        uint32_t a0 = SA[(f0 + g)     * KSTR + k0 + t];
        uint32_t a1 = SA[(f0 + g + 8) * KSTR + k0 + t];
        uint32_t a2 = SA[(f0 + g)     * KSTR + k0 + t + 4];
        uint32_t a3 = SA[(f0 + g + 8) * KSTR + k0 + t + 4];
        #pragma unroll
        for (int ns = 0; ns < 8; ns++) {
            uint32_t b0 = SB[(ns * 8 + g) * KSTR + k0 + t];
            uint32_t b1 = SB[(ns * 8 + g) * KSTR + k0 + t + 4];
            asm volatile(
                "mma.sync.aligned.m16n8k8.row.col.f32.tf32.tf32.f32 "
                "{%0,%1,%2,%3}, {%4,%5,%6,%7}, {%8,%9}, {%0,%1,%2,%3};"
                : "+f"(acc[ns][0]), "+f"(acc[ns][1]), "+f"(acc[ns][2]), "+f"(acc[ns][3])
                : "r"(a0), "r"(a1), "r"(a2), "r"(a3), "r"(b0), "r"(b1));
        }
    }

    // ---- epilogue: D(f,px) - 0.5*(x2+w2); direct 8B stores ----
    {
        const int f_lo = f0 + g, f_hi = f0 + g + 8;
        const float w2lo = Sf[W2_OFF / 4 + f_lo];
        const float w2hi = Sf[W2_OFF / 4 + f_hi];
        const float* x2s = Sf + X2_OFF / 4 + ncol * 64;
        float* oplo = out + (((long)(n * F + f_lo) * HW) + (r0 + ncol)) * HW;
        float* ophi = out + (((long)(n * F + f_hi) * HW) + (r0 + ncol)) * HW;

        #pragma unroll
        for (int ns = 0; ns < 8; ns++) {
            int wo = ns * 8 + 2 * t;
            float xa = x2s[wo], xb = x2s[wo + 1];
            float2 vlo = make_float2(acc[ns][0] - 0.5f * (xa + w2lo),
                                     acc[ns][1] - 0.5f * (xb + w2lo));
            float2 vhi = make_float2(acc[ns][2] - 0.5f * (xa + w2hi),
                                     acc[ns][3] - 0.5f * (xb + w2hi));
            *(float2*)(oplo + wo) = vlo;
            *(float2*)(ophi + wo) = vhi;
        }
    }
}

extern "C" void kernel_launch(void* const* d_in, const int* in_sizes, int n_in,
                              void* d_out, int out_size) {
    const float* x = (const float*)d_in[0];
    const float* W = (const float*)d_in[1];
    float* out = (float*)d_out;

    cudaFuncSetAttribute(euclid2d_kernel,
                         cudaFuncAttributeMaxDynamicSharedMemorySize, SMEM_BYTES);
    dim3 grid(HW / 2, 8);    // 256 CTAs (2-row tiles)
    euclid2d_kernel<<<grid, NTHR, SMEM_BYTES>>>(x, W, out);
}

// round 17
// speedup vs baseline: 2.2730x; 1.3534x over previous
#include <cuda_runtime.h>
#include <cstdint>

#define HW   64
#define F    64
#define D    75
#define KSTR 84          // conflict-free fragment loads: (g*84+t) mod 32 all distinct
#define NTHR 256

// byte offsets in dynamic smem
#define A_OFF   0        // W tf32 [64][84]   = 21504 B
#define B_OFF   21504    // Xcol tf32 [128][84] = 43008 B
#define XT_OFF  64512    // xtile [3][6][68] f32 = 4896 B
#define X2P_OFF 69408    // x2 partials [2][128]
#define X2_OFF  70432    // x2[128]
#define W2P_OFF 70944    // w2 partials [4][64]
#define W2_OFF  71968    // w2[64]
#define SMEM_BYTES 72224

__device__ __forceinline__ uint32_t to_tf32(float v) {
    uint32_t r;
    asm("cvt.rna.tf32.f32 %0, %1;" : "=r"(r) : "f"(v));
    return r;
}

__global__ __launch_bounds__(NTHR)
void euclid2d_kernel(const float* __restrict__ x,
                     const float* __restrict__ W,
                     float* __restrict__ out) {
    extern __shared__ __align__(16) char smem[];
    float* Sf = (float*)smem;
    uint32_t* Su = (uint32_t*)smem;

    const int tid  = threadIdx.x;
    const int lane = tid & 31;
    const int wid  = tid >> 5;
    const int r0   = blockIdx.x * 2;   // output rows r0, r0+1
    const int n    = blockIdx.y;

    // ---- zero ONLY the K-pad (k=75..79) of A(64 rows) + B(128 rows) ----
    #pragma unroll
    for (int i = 0; i < 4; i++) {
        int j = tid + i * NTHR;             // 0..959
        if (j < 960) {
            int row = j / 5, kk = 75 + j % 5;
            if (row < 64) Su[A_OFF / 4 + row * KSTR + kk] = 0u;
            else          Su[B_OFF / 4 + (row - 64) * KSTR + kk] = 0u;
        }
    }
    // ---- x tile [3][6][68] ----
    {
        float* xt = Sf + XT_OFF / 4;
        const int y0 = r0 - 2;
        #pragma unroll
        for (int i = 0; i < 5; i++) {
            int idx = tid + i * NTHR;       // 0..1223
            if (idx < 3 * 6 * 68) {
                int c = idx / 408, rr = (idx / 68) % 6, col = idx % 68;
                int gy = y0 + rr, gx = col - 2;
                float v = 0.0f;
                if (gy >= 0 && gy < HW && gx >= 0 && gx < HW)
                    v = x[((n * 3 + c) * HW + gy) * HW + gx];
                xt[idx] = v;
            }
        }
    }
    __syncthreads();   // S1

    // ---- A = tf32(W): coalesced LDG ----
    #pragma unroll
    for (int i = 0; i < 19; i++) {
        int idx = tid + i * NTHR;
        if (idx < F * D) {
            int f = idx / D, k = idx % D;
            Su[A_OFF / 4 + f * KSTR + k] = to_tf32(W[idx]);
        }
    }
    // ---- B = tf32(im2col): warp-uniform k-half, COMPILE-TIME k ----
    {
        const int half = tid >> 7;          // warps 0-3: k 0..37, warps 4-7: 38..74
        const int px   = tid & 127;
        const int r    = px >> 6, p = px & 63;
        const float* xb = Sf + XT_OFF / 4 + r * 68 + p;
        uint32_t* brow = Su + B_OFF / 4 + px * KSTR;
        float s = 0.0f;
        if (half == 0) {
            #pragma unroll
            for (int k = 0; k < 38; k++) {
                const int c = k / 25, kh = (k % 25) / 5, kw = k % 5;   // constants
                float v = xb[(c * 6 + kh) * 68 + kw];
                brow[k] = to_tf32(v);
                s += v * v;
            }
        } else {
            #pragma unroll
            for (int k = 38; k < 75; k++) {
                const int c = k / 25, kh = (k % 25) / 5, kw = k % 5;   // constants
                float v = xb[(c * 6 + kh) * 68 + kw];
                brow[k] = to_tf32(v);
                s += v * v;
            }
        }
        Sf[X2P_OFF / 4 + half * 128 + px] = s;
    }
    __syncthreads();   // S2: A, B, X2P ready

    // ---- w2 partials from smem tf32 A (no gmem gather) ----
    {
        int f = tid & 63, q = tid >> 6;
        float s = 0.0f;
        #pragma unroll
        for (int i = 0; i < 19; i++) {
            int d = q + 4 * i;
            if (d < D) {
                float wv = Sf[A_OFF / 4 + f * KSTR + d];   // tf32 value as f32
                s += wv * wv;
            }
        }
        Sf[W2P_OFF / 4 + q * 64 + f] = s;
    }
    __syncthreads();   // S3: W2P ready

    // ---- reduces: X2 (tid<128), W2 (tid 128..191) ----
    if (tid < 128) {
        Sf[X2_OFF / 4 + tid] = Sf[X2P_OFF / 4 + tid] + Sf[X2P_OFF / 4 + 128 + tid];
    } else if (tid < 192) {
        int f = tid - 128;
        Sf[W2_OFF / 4 + f] = Sf[W2P_OFF / 4 + f] + Sf[W2P_OFF / 4 + 64 + f]
                           + Sf[W2P_OFF / 4 + 128 + f] + Sf[W2P_OFF / 4 + 192 + f];
    }
    __syncthreads();   // S4: X2, W2 ready

    // ---- MMA: wid = mrow(0..3) + 4*ncol(0..1); warp tile M16 x N64 ----
    const int mrow = wid & 3;
    const int ncol = wid >> 2;
    const int f0   = mrow * 16;
    const int g    = lane >> 2;
    const int t    = lane & 3;

    float acc[8][4];
    #pragma unroll
    for (int s = 0; s < 8; s++)
        #pragma unroll
        for (int j = 0; j < 4; j++) acc[s][j] = 0.0f;

    const uint32_t* SA = Su + A_OFF / 4;
    const uint32_t* SB = Su + B_OFF / 4 + (ncol * 64) * KSTR;

    #pragma unroll
    for (int ks = 0; ks < 10; ks++) {
        const int k0 = ks * 8;
        uint32_t a0 = SA[(f0 + g)     * KSTR + k0 + t];
        uint32_t a1 = SA[(f0 + g + 8) * KSTR + k0 + t];
        uint32_t a2 = SA[(f0 + g)     * KSTR + k0 + t + 4];
        uint32_t a3 = SA[(f0 + g + 8) * KSTR + k0 + t + 4];
        #pragma unroll
        for (int ns = 0; ns < 8; ns++) {
            uint32_t b0 = SB[(ns * 8 + g) * KSTR + k0 + t];
            uint32_t b1 = SB[(ns * 8 + g) * KSTR + k0 + t + 4];
            asm volatile(
                "mma.sync.aligned.m16n8k8.row.col.f32.tf32.tf32.f32 "
                "{%0,%1,%2,%3}, {%4,%5,%6,%7}, {%8,%9}, {%0,%1,%2,%3};"
                : "+f"(acc[ns][0]), "+f"(acc[ns][1]), "+f"(acc[ns][2]), "+f"(acc[ns][3])
                : "r"(a0), "r"(a1), "r"(a2), "r"(a3), "r"(b0), "r"(b1));
        }
    }

    // ---- epilogue: D(f,px) - 0.5*(x2+w2); direct 8B stores ----
    {
        const int f_lo = f0 + g, f_hi = f0 + g + 8;
        const float w2lo = Sf[W2_OFF / 4 + f_lo];
        const float w2hi = Sf[W2_OFF / 4 + f_hi];
        const float* x2s = Sf + X2_OFF / 4 + ncol * 64;
        float* oplo = out + (((long)(n * F + f_lo) * HW) + (r0 + ncol)) * HW;
        float* ophi = out + (((long)(n * F + f_hi) * HW) + (r0 + ncol)) * HW;

        #pragma unroll
        for (int ns = 0; ns < 8; ns++) {
            int wo = ns * 8 + 2 * t;
            float xa = x2s[wo], xb = x2s[wo + 1];
            float2 vlo = make_float2(acc[ns][0] - 0.5f * (xa + w2lo),
                                     acc[ns][1] - 0.5f * (xb + w2lo));
            float2 vhi = make_float2(acc[ns][2] - 0.5f * (xa + w2hi),
                                     acc[ns][3] - 0.5f * (xb + w2hi));
            *(float2*)(oplo + wo) = vlo;
            *(float2*)(ophi + wo) = vhi;
        }
    }
}

extern "C" void kernel_launch(void* const* d_in, const int* in_sizes, int n_in,
                              void* d_out, int out_size) {
    const float* x = (const float*)d_in[0];
    const float* W = (const float*)d_in[1];
    float* out = (float*)d_out;

    cudaFuncSetAttribute(euclid2d_kernel,
                         cudaFuncAttributeMaxDynamicSharedMemorySize, SMEM_BYTES);
    dim3 grid(HW / 2, 8);    // 256 CTAs (2-row tiles)
    euclid2d_kernel<<<grid, NTHR, SMEM_BYTES>>>(x, W, out);
}